// round 16
// baseline (speedup 1.0000x reference)
#include <cuda_runtime.h>
#include <cuda_fp16.h>
#include <math.h>
#include <stdint.h>

#define N_TOK   4096
#define D_MODEL 1024
#define D_FF    2048
#define N_EXP   8
#define ROWS    9216
#define TILE    128
#define BK      64
#define LDA     72          /* padded SMEM row stride in halves (144B, conflict-free ldmatrix) */

#define BUF_BYTES   (128 * LDA * 2)          /* 18432 B per tile buffer */
#define A_OFF       0
#define B_OFF       (1 * BUF_BYTES)
#define STAGE_BYTES (2 * BUF_BYTES)          /* 36864 B */
#define NSTAGE      3
#define DSMEM_BYTES (NSTAGE * STAGE_BYTES)   /* 110592 B; x2 blocks = 221184 <= 228KB */

// ===================== helpers ==============================================
__device__ __forceinline__ uint32_t smem_u32(const void* p) {
    uint32_t a;
    asm("{ .reg .u64 t; cvta.to.shared.u64 t, %1; cvt.u32.u64 %0, t; }" : "=r"(a) : "l"(p));
    return a;
}
__device__ __forceinline__ void ldsm_x4(uint32_t& r0, uint32_t& r1, uint32_t& r2, uint32_t& r3,
                                        uint32_t addr) {
    asm volatile("ldmatrix.sync.aligned.m8n8.x4.shared.b16 {%0,%1,%2,%3}, [%4];"
                 : "=r"(r0), "=r"(r1), "=r"(r2), "=r"(r3) : "r"(addr));
}
__device__ __forceinline__ void mma16816(float* c, const uint32_t* a, uint32_t b0, uint32_t b1) {
    asm volatile(
        "mma.sync.aligned.m16n8k16.row.col.f32.f16.f16.f32 "
        "{%0,%1,%2,%3}, {%4,%5,%6,%7}, {%8,%9}, {%0,%1,%2,%3};"
        : "+f"(c[0]), "+f"(c[1]), "+f"(c[2]), "+f"(c[3])
        : "r"(a[0]), "r"(a[1]), "r"(a[2]), "r"(a[3]), "r"(b0), "r"(b1));
}
__device__ __forceinline__ void cp16(uint32_t saddr, const void* g, uint32_t src_sz) {
    asm volatile("cp.async.cg.shared.global [%0], [%1], 16, %2;"
                 :: "r"(saddr), "l"(g), "r"(src_sz));
}
#define CP_COMMIT() asm volatile("cp.async.commit_group;" ::: "memory")
#define CP_WAIT1()  asm volatile("cp.async.wait_group 1;" ::: "memory")

// ===================== scratch ==============================================
__device__ int   d_tok_exp[N_TOK * 2];
__device__ float d_tok_w[N_TOK * 2];
__device__ int   d_count[N_EXP];
__device__ int   d_off[N_EXP + 1];
__device__ int   d_cursor[N_EXP];
__device__ int   d_row_token[ROWS];
__device__ float d_row_weight[ROWS];

__device__ __half d_x16[(size_t)N_TOK * D_MODEL];
__device__ __half d_wgu16[(size_t)N_EXP * 2 * D_FF * D_MODEL];
__device__ __half d_wd16[(size_t)N_EXP * D_MODEL * D_FF];
__device__ __half d_H[(size_t)ROWS * D_FF];

// ===================== small kernels ========================================
__global__ void init_kernel(float* __restrict__ out) {
    int i = blockIdx.x * blockDim.x + threadIdx.x;
    int stride = gridDim.x * blockDim.x;
    for (int j = i; j < N_TOK * D_MODEL; j += stride) out[j] = 0.f;
    if (i < ROWS) { d_row_token[i] = -1; d_row_weight[i] = 0.f; }
    if (i < N_EXP) d_count[i] = 0;
}

// fp32 -> fp16
__global__ void cvt16_kernel(const float* __restrict__ s, __half* __restrict__ o, int n4) {
    int i = blockIdx.x * blockDim.x + threadIdx.x;
    if (i >= n4) return;
    float4 v = reinterpret_cast<const float4*>(s)[i];
    reinterpret_cast<__half2*>(o)[2 * i]     = __floats2half2_rn(v.x, v.y);
    reinterpret_cast<__half2*>(o)[2 * i + 1] = __floats2half2_rn(v.z, v.w);
}

__global__ void router_kernel(const float* __restrict__ x,
                              const float* __restrict__ wr) {
    int warp = (blockIdx.x * blockDim.x + threadIdx.x) >> 5;
    int lane = threadIdx.x & 31;
    if (warp >= N_TOK) return;
    const float* xr = x + (size_t)warp * D_MODEL;

    float logits[N_EXP];
#pragma unroll
    for (int e = 0; e < N_EXP; e++) {
        const float* w = wr + e * D_MODEL;
        float p = 0.f;
        for (int d = lane; d < D_MODEL; d += 32) p = fmaf(xr[d], w[d], p);
#pragma unroll
        for (int s = 16; s > 0; s >>= 1) p += __shfl_xor_sync(0xffffffffu, p, s);
        logits[e] = p;
    }
    if (lane == 0) {
        float mx = -3.4e38f;
#pragma unroll
        for (int e = 0; e < N_EXP; e++) {
            float v = fminf(fmaxf(logits[e], -1e4f), 1e4f);
            logits[e] = v; mx = fmaxf(mx, v);
        }
        float ex[N_EXP], s = 0.f;
#pragma unroll
        for (int e = 0; e < N_EXP; e++) { ex[e] = expf(logits[e] - mx); s += ex[e]; }
        float denom = s + 1e-8f;
        float probs[N_EXP];
#pragma unroll
        for (int e = 0; e < N_EXP; e++)
            probs[e] = fminf(fmaxf(ex[e] / denom, 1e-8f), 1.0f);
        int i0 = 0;
#pragma unroll
        for (int e = 1; e < N_EXP; e++) if (probs[e] > probs[i0]) i0 = e;
        int i1 = (i0 == 0) ? 1 : 0;
#pragma unroll
        for (int e = 0; e < N_EXP; e++)
            if (e != i0 && probs[e] > probs[i1]) i1 = e;
        float p0 = probs[i0], p1 = probs[i1];
        float rs = 1.f / (p0 + p1 + 1e-8f);
        d_tok_exp[2 * warp] = i0;  d_tok_exp[2 * warp + 1] = i1;
        d_tok_w[2 * warp] = p0 * rs; d_tok_w[2 * warp + 1] = p1 * rs;
        atomicAdd(&d_count[i0], 1); atomicAdd(&d_count[i1], 1);
    }
}

__global__ void offsets_kernel() {
    if (threadIdx.x == 0) {
        int o = 0;
        for (int e = 0; e < N_EXP; e++) {
            d_off[e] = o;
            o += ((d_count[e] + TILE - 1) / TILE) * TILE;
            d_cursor[e] = 0;
        }
        d_off[N_EXP] = o;
    }
}

__global__ void scatter_kernel() {
    int t = blockIdx.x * blockDim.x + threadIdx.x;
    if (t >= N_TOK) return;
#pragma unroll
    for (int k = 0; k < 2; k++) {
        int e = d_tok_exp[2 * t + k];
        int pos = d_off[e] + atomicAdd(&d_cursor[e], 1);
        d_row_token[pos]  = t;
        d_row_weight[pos] = d_tok_w[2 * t + k];
    }
}

// ===================== GEMM1: x(gather) @ wgu^T + fused SwiGLU -> d_H ========
// grid: (D_FF/64, ROWS/128). B rows interleaved: even = gate(f), odd = up(f).
// Pure fp16 HMMA, fp32 accumulate. 2 blocks/SM, BK=64, 3-stage cp.async.
__global__ __launch_bounds__(256, 2)
void gemm1_mma(void) {
    extern __shared__ __align__(16) char dyn[];
    __shared__ int stok[128];

    const int tid  = threadIdx.x;
    const int wid  = tid >> 5;
    const int lane = tid & 31;
    const int rowStart  = blockIdx.y * 128;
    const int colStartF = blockIdx.x * 64;

    if (rowStart >= d_off[N_EXP]) return;
    int e = 0;
#pragma unroll
    for (int i = N_EXP - 1; i >= 0; i--) if (rowStart >= d_off[i]) { e = i; break; }

    if (tid < 128) stok[tid] = d_row_token[rowStart + tid];
    __syncthreads();

    const size_t wb = (size_t)e * 2 * D_FF * D_MODEL;
    const int wm = (wid & 1) * 64;
    const int wn = (wid >> 1) * 32;
    const uint32_t base = smem_u32(dyn);

    // per-thread load coords: one row per 2 threads, 4 x 16B units each
    const int r_  = tid >> 1;                 // 0..127
    const int ub_ = (tid & 1) * 4;            // unit base 0 or 4
    const int rr_ = colStartF + (r_ >> 1) + (r_ & 1) * D_FF;
    const int t_  = stok[r_];
    const uint32_t szA = (t_ >= 0) ? 16u : 0u;
    const size_t gaBase = (size_t)(t_ >= 0 ? t_ : 0) * D_MODEL;
    const size_t gbBase = wb + (size_t)rr_ * D_MODEL;

    float acc[4][4][4];
#pragma unroll
    for (int a = 0; a < 4; a++)
#pragma unroll
        for (int b = 0; b < 4; b++)
#pragma unroll
            for (int c = 0; c < 4; c++) acc[a][b][c] = 0.f;

#define G1_LOAD(stage, kt) do {                                                   \
    const uint32_t sb = base + (stage) * STAGE_BYTES;                             \
    const int k0 = (kt) * BK;                                                     \
    _Pragma("unroll")                                                             \
    for (int j = 0; j < 4; j++) {                                                 \
        int u8 = ub_ + j;                                                         \
        uint32_t so = (uint32_t)((r_ * LDA + u8 * 8) * 2);                        \
        cp16(sb + A_OFF + so, d_x16 + gaBase + k0 + u8 * 8, szA);                 \
        cp16(sb + B_OFF + so, d_wgu16 + gbBase + k0 + u8 * 8, 16u);               \
    }                                                                             \
} while (0)

    G1_LOAD(0, 0);
    CP_COMMIT();
    G1_LOAD(1, 1);
    CP_COMMIT();

    const int NKT = D_MODEL / BK;
#pragma unroll 1
    for (int kt = 0; kt < NKT; kt++) {
        CP_WAIT1();
        __syncthreads();
        if (kt + 2 < NKT) G1_LOAD((kt + 2) % NSTAGE, kt + 2);
        CP_COMMIT();

        const uint32_t sb = base + (kt % NSTAGE) * STAGE_BYTES;
        const uint32_t aA = sb + A_OFF, aB = sb + B_OFF;
#pragma unroll
        for (int ks = 0; ks < BK / 16; ks++) {
            const int kk = ks * 16;
            uint32_t fA[4][4], fB[2][4];
#pragma unroll
            for (int mt = 0; mt < 4; mt++) {
                uint32_t off = (uint32_t)(((wm + mt * 16 + (lane & 15)) * LDA
                                           + kk + (lane >> 4) * 8) * 2);
                ldsm_x4(fA[mt][0], fA[mt][1], fA[mt][2], fA[mt][3], aA + off);
            }
#pragma unroll
            for (int p = 0; p < 2; p++) {
                int n0 = wn + p * 16;
                uint32_t off = (uint32_t)(((n0 + (lane & 7) + (lane >> 4) * 8) * LDA
                                           + kk + ((lane >> 3) & 1) * 8) * 2);
                ldsm_x4(fB[p][0], fB[p][1], fB[p][2], fB[p][3], aB + off);
            }
#pragma unroll
            for (int mt = 0; mt < 4; mt++)
#pragma unroll
                for (int nb = 0; nb < 4; nb++) {
                    int p = nb >> 1, h = (nb & 1) * 2;
                    mma16816(acc[mt][nb], fA[mt], fB[p][h], fB[p][h + 1]);
                }
        }
    }
#undef G1_LOAD

    // fused SwiGLU epilogue: column pair = (gate, up) of f = colStartF + col/2
    const int g  = lane >> 2;
    const int c2 = (lane & 3) * 2;
#pragma unroll
    for (int mt = 0; mt < 4; mt++) {
        int row0 = rowStart + wm + mt * 16 + g;
#pragma unroll
        for (int nb = 0; nb < 4; nb++) {
            int fcol = colStartF + ((wn + nb * 8 + c2) >> 1);
            float g0 = acc[mt][nb][0], u0 = acc[mt][nb][1];
            float g1 = acc[mt][nb][2], u1 = acc[mt][nb][3];
            float h0 = g0 * u0 / (1.f + expf(-u0));
            float h1 = g1 * u1 / (1.f + expf(-u1));
            d_H[(size_t)row0 * D_FF + fcol]       = __float2half_rn(h0);
            d_H[(size_t)(row0 + 8) * D_FF + fcol] = __float2half_rn(h1);
        }
    }
}

// ===================== GEMM2: H @ wd^T -> weighted scatter ===================
// grid: (1024/128, ROWS/128). K = 2048. Pure fp16 HMMA. 2 blocks/SM, BK=64.
__global__ __launch_bounds__(256, 2)
void gemm2_mma(float* __restrict__ out) {
    extern __shared__ __align__(16) char dyn[];
    __shared__ int   stok[128];
    __shared__ float swt[128];

    const int tid  = threadIdx.x;
    const int wid  = tid >> 5;
    const int lane = tid & 31;
    const int rowStart = blockIdx.y * 128;
    const int colStart = blockIdx.x * 128;

    if (rowStart >= d_off[N_EXP]) return;
    int e = 0;
#pragma unroll
    for (int i = N_EXP - 1; i >= 0; i--) if (rowStart >= d_off[i]) { e = i; break; }

    if (tid < 128) {
        stok[tid] = d_row_token[rowStart + tid];
        swt[tid]  = d_row_weight[rowStart + tid];
    }
    __syncthreads();

    const size_t wb = (size_t)e * D_MODEL * D_FF;
    const int wm = (wid & 1) * 64;
    const int wn = (wid >> 1) * 32;
    const uint32_t base = smem_u32(dyn);

    const int r_  = tid >> 1;
    const int ub_ = (tid & 1) * 4;
    const size_t gaBase = (size_t)(rowStart + r_) * D_FF;
    const size_t gbBase = wb + (size_t)(colStart + r_) * D_FF;

    float acc[4][4][4];
#pragma unroll
    for (int a = 0; a < 4; a++)
#pragma unroll
        for (int b = 0; b < 4; b++)
#pragma unroll
            for (int c = 0; c < 4; c++) acc[a][b][c] = 0.f;

#define G2_LOAD(stage, kt) do {                                                   \
    const uint32_t sb = base + (stage) * STAGE_BYTES;                             \
    const int k0 = (kt) * BK;                                                     \
    _Pragma("unroll")                                                             \
    for (int j = 0; j < 4; j++) {                                                 \
        int u8 = ub_ + j;                                                         \
        uint32_t so = (uint32_t)((r_ * LDA + u8 * 8) * 2);                        \
        cp16(sb + A_OFF + so, d_H + gaBase + k0 + u8 * 8, 16u);                   \
        cp16(sb + B_OFF + so, d_wd16 + gbBase + k0 + u8 * 8, 16u);                \
    }                                                                             \
} while (0)

    G2_LOAD(0, 0);
    CP_COMMIT();
    G2_LOAD(1, 1);
    CP_COMMIT();

    const int NKT = D_FF / BK;
#pragma unroll 1
    for (int kt = 0; kt < NKT; kt++) {
        CP_WAIT1();
        __syncthreads();
        if (kt + 2 < NKT) G2_LOAD((kt + 2) % NSTAGE, kt + 2);
        CP_COMMIT();

        const uint32_t sb = base + (kt % NSTAGE) * STAGE_BYTES;
        const uint32_t aA = sb + A_OFF, aB = sb + B_OFF;
#pragma unroll
        for (int ks = 0; ks < BK / 16; ks++) {
            const int kk = ks * 16;
            uint32_t fA[4][4], fB[2][4];
#pragma unroll
            for (int mt = 0; mt < 4; mt++) {
                uint32_t off = (uint32_t)(((wm + mt * 16 + (lane & 15)) * LDA
                                           + kk + (lane >> 4) * 8) * 2);
                ldsm_x4(fA[mt][0], fA[mt][1], fA[mt][2], fA[mt][3], aA + off);
            }
#pragma unroll
            for (int p = 0; p < 2; p++) {
                int n0 = wn + p * 16;
                uint32_t off = (uint32_t)(((n0 + (lane & 7) + (lane >> 4) * 8) * LDA
                                           + kk + ((lane >> 3) & 1) * 8) * 2);
                ldsm_x4(fB[p][0], fB[p][1], fB[p][2], fB[p][3], aB + off);
            }
#pragma unroll
            for (int mt = 0; mt < 4; mt++)
#pragma unroll
                for (int nb = 0; nb < 4; nb++) {
                    int p = nb >> 1, h = (nb & 1) * 2;
                    mma16816(acc[mt][nb], fA[mt], fB[p][h], fB[p][h + 1]);
                }
        }
    }
#undef G2_LOAD

    // epilogue: weighted scatter-add (each out element gets exactly 2 fp32 adds)
    const int g  = lane >> 2;
    const int c2 = (lane & 3) * 2;
#pragma unroll
    for (int mt = 0; mt < 4; mt++) {
        int r0 = wm + mt * 16 + g;
        int t0 = stok[r0],     t1 = stok[r0 + 8];
        float w0 = swt[r0],    w1 = swt[r0 + 8];
#pragma unroll
        for (int nb = 0; nb < 4; nb++) {
            int col = colStart + wn + nb * 8 + c2;
            if (t0 >= 0) {
                float* o = out + (size_t)t0 * D_MODEL + col;
                atomicAdd(o,     w0 * acc[mt][nb][0]);
                atomicAdd(o + 1, w0 * acc[mt][nb][1]);
            }
            if (t1 >= 0) {
                float* o = out + (size_t)t1 * D_MODEL + col;
                atomicAdd(o,     w1 * acc[mt][nb][2]);
                atomicAdd(o + 1, w1 * acc[mt][nb][3]);
            }
        }
    }
}

// ===================== launch ================================================
extern "C" void kernel_launch(void* const* d_in, const int* in_sizes, int n_in,
                              void* d_out, int out_size) {
    const float* x   = (const float*)d_in[0];
    const float* wr  = (const float*)d_in[1];
    const float* wgu = (const float*)d_in[2];
    const float* wd  = (const float*)d_in[3];
    float* out = (float*)d_out;

    cudaFuncSetAttribute(gemm1_mma, cudaFuncAttributeMaxDynamicSharedMemorySize, DSMEM_BYTES);
    cudaFuncSetAttribute(gemm2_mma, cudaFuncAttributeMaxDynamicSharedMemorySize, DSMEM_BYTES);

    init_kernel<<<2048, 512>>>(out);

    __half *x16, *wgu16, *wd16;
    cudaGetSymbolAddress((void**)&x16,   d_x16);
    cudaGetSymbolAddress((void**)&wgu16, d_wgu16);
    cudaGetSymbolAddress((void**)&wd16,  d_wd16);

    { int n4 = N_TOK * D_MODEL / 4;
      cvt16_kernel<<<(n4 + 255) / 256, 256>>>(x, x16, n4); }
    { int n4 = N_EXP * 2 * D_FF * D_MODEL / 4;
      cvt16_kernel<<<(n4 + 255) / 256, 256>>>(wgu, wgu16, n4); }
    { int n4 = N_EXP * D_MODEL * D_FF / 4;
      cvt16_kernel<<<(n4 + 255) / 256, 256>>>(wd, wd16, n4); }

    router_kernel<<<N_TOK / 8, 256>>>(x, wr);
    offsets_kernel<<<1, 32>>>();
    scatter_kernel<<<(N_TOK + 255) / 256, 256>>>();

    gemm1_mma<<<dim3(D_FF / 64, ROWS / 128), 256, DSMEM_BYTES>>>();
    gemm2_mma<<<dim3(D_MODEL / 128, ROWS / 128), 256, DSMEM_BYTES>>>(out);
}